// round 13
// baseline (speedup 1.0000x reference)
#include <cuda_runtime.h>

// RateBasedNeuron: N=2^23 neuron sim, warp-autonomous formulation (v9).
//  rate[t] = a*rate[t-1] + alpha*I[t]  (a = 1-1/tau, contractive)
//  p[t] = clip(rate/thr,0,1)*0.1 ; 3-state refractory DFA -> spikes.
//
// Each WARP owns an independent 1536-elem tile + 512-elem halo. 8 serial
// segments of 256; each lane owns 8 consecutive elems (two float4); IIR
// B-scan with constant round multipliers + DFA state-map scan via shuffles,
// scalar carries between segments. DFA per-lane work via 256-entry shared
// LUT (spike masks for 3 incoming states + byte-packed transition map).
//
// v9: WTILE 2048->1536 (grid was the occupancy limiter: 27.7 warps/SM ->
// 36.9), explicit prefetch queue dropped (regs -16, rely on warp
// parallelism), __launch_bounds__(256,5) to lift the reg-based warp cap.

#define WSEG    256
#define NSEG    8
#define WREGION (WSEG * NSEG)        // 2048
#define WHALO   512
#define HSEG    (WHALO / WSEG)       // 2
#define WTILE   (WREGION - WHALO)    // 1536
#define THREADS 256
#define FULLMASK 0xffffffffu

// compose byte-packed 3-state maps: apply g first, then f. h[i] = f[g[i]].
// __byte_perm selector = nibbles -> compress g's bytes into nibbles first.
__device__ __forceinline__ unsigned dfa_compose(unsigned f, unsigned g) {
    unsigned sel = (g & 3u) | ((g >> 4) & 0x30u) | ((g >> 8) & 0x300u);
    return __byte_perm(f, 0, sel);
}

template <bool INTERIOR>
__device__ __forceinline__ void run_warp(
    const float* __restrict__ gI, const float* __restrict__ gU,
    float* __restrict__ gOut, const uint2* __restrict__ tbl,
    long long base, long long N,
    float alpha, float a, float rthr, int lane)
{
    // powers of a: scan round multipliers (lane span = 8 elems)
    const float a2   = a * a;
    const float a4   = a2 * a2;
    const float c1   = a4 * a4;      // a^8
    const float c2   = c1 * c1;      // a^16
    const float c4   = c2 * c2;      // a^32
    const float c8   = c4 * c4;      // a^64
    const float c16  = c8 * c8;      // a^128
    const float cSeg = c16 * c16;    // a^256
    float aL = 1.0f, bp = c1;        // aL = a^{8*lane}
    #pragma unroll
    for (int bit = 0; bit < 5; bit++) {
        if (lane & (1 << bit)) aL *= bp;
        bp *= bp;
    }

    float    rcar = 0.0f;   // IIR carry entering current segment
    unsigned scar = 0u;     // DFA carry state in {0,1,2}

    const float4* pI4 = (const float4*)(gI + base);
    const float4* pU4 = (const float4*)(gU + base);
    float4*       pO4 = (float4*)(gOut + base);
    const int li = 2 * lane;

    #pragma unroll 1
    for (int seg = 0; seg < NSEG; seg++) {
        float4 cb0, cb1, cu0, cu1;
        if (INTERIOR) {
            const int ix = seg * (WSEG / 4) + li;
            cb0 = pI4[ix]; cb1 = pI4[ix + 1];
            cu0 = pU4[ix]; cu1 = pU4[ix + 1];
        } else {
            long long gg = base + (long long)seg * WSEG + lane * 8;
            float tmpb[8], tmpu[8];
            #pragma unroll
            for (int t = 0; t < 8; t++) {
                long long g = gg + t;
                tmpb[t] = (g >= 1 && g < N) ? gI[g] : 0.0f;
                tmpu[t] = (g >= 0 && g < N) ? gU[g] : 1.0f;
            }
            cb0 = make_float4(tmpb[0], tmpb[1], tmpb[2], tmpb[3]);
            cb1 = make_float4(tmpb[4], tmpb[5], tmpb[6], tmpb[7]);
            cu0 = make_float4(tmpu[0], tmpu[1], tmpu[2], tmpu[3]);
            cu1 = make_float4(tmpu[4], tmpu[5], tmpu[6], tmpu[7]);
        }

        const float b0 = alpha * cb0.x, b1 = alpha * cb0.y;
        const float b2 = alpha * cb0.z, b3 = alpha * cb0.w;
        const float b4 = alpha * cb1.x, b5 = alpha * cb1.y;
        const float b6 = alpha * cb1.z, b7 = alpha * cb1.w;

        // ---- lane-local affine reduce (8 elems) ----
        float B = b0;
        B = fmaf(B, a, b1); B = fmaf(B, a, b2); B = fmaf(B, a, b3);
        B = fmaf(B, a, b4); B = fmaf(B, a, b5); B = fmaf(B, a, b6);
        B = fmaf(B, a, b7);

        // ---- warp inclusive B-scan, constant round multipliers ----
        float Bi = B, Bu;
        Bu = __shfl_up_sync(FULLMASK, Bi, 1);  if (lane >= 1)  Bi = fmaf(Bu, c1,  Bi);
        Bu = __shfl_up_sync(FULLMASK, Bi, 2);  if (lane >= 2)  Bi = fmaf(Bu, c2,  Bi);
        Bu = __shfl_up_sync(FULLMASK, Bi, 4);  if (lane >= 4)  Bi = fmaf(Bu, c4,  Bi);
        Bu = __shfl_up_sync(FULLMASK, Bi, 8);  if (lane >= 8)  Bi = fmaf(Bu, c8,  Bi);
        Bu = __shfl_up_sync(FULLMASK, Bi, 16); if (lane >= 16) Bi = fmaf(Bu, c16, Bi);
        float Be  = __shfl_up_sync(FULLMASK, Bi, 1);
        if (lane == 0) Be = 0.0f;
        float B31 = __shfl_sync(FULLMASK, Bi, 31);
        float rin = fmaf(aL, rcar, Be);
        rcar = fmaf(cSeg, rcar, B31);

        // ---- rates -> p -> eligibility bits (r >= 0, fmax elided) ----
        float r = rin, q;
        unsigned e = 0;
        r = fmaf(a, r, b0); q = fminf(r * rthr, 1.0f) * 0.1f; e |= (cu0.x < q ?   1u : 0u);
        r = fmaf(a, r, b1); q = fminf(r * rthr, 1.0f) * 0.1f; e |= (cu0.y < q ?   2u : 0u);
        r = fmaf(a, r, b2); q = fminf(r * rthr, 1.0f) * 0.1f; e |= (cu0.z < q ?   4u : 0u);
        r = fmaf(a, r, b3); q = fminf(r * rthr, 1.0f) * 0.1f; e |= (cu0.w < q ?   8u : 0u);
        r = fmaf(a, r, b4); q = fminf(r * rthr, 1.0f) * 0.1f; e |= (cu1.x < q ?  16u : 0u);
        r = fmaf(a, r, b5); q = fminf(r * rthr, 1.0f) * 0.1f; e |= (cu1.y < q ?  32u : 0u);
        r = fmaf(a, r, b6); q = fminf(r * rthr, 1.0f) * 0.1f; e |= (cu1.z < q ?  64u : 0u);
        r = fmaf(a, r, b7); q = fminf(r * rthr, 1.0f) * 0.1f; e |= (cu1.w < q ? 128u : 0u);

        // ---- DFA via LUT: spike masks (3 states) + byte-packed map ----
        uint2 en = tbl[e];

        // ---- warp scan of state maps (exact compose) ----
        unsigned Fi = en.y;
        #pragma unroll
        for (int d = 1; d < 32; d <<= 1) {
            unsigned Fu = __shfl_up_sync(FULLMASK, Fi, d);
            if (lane >= d) Fi = dfa_compose(Fi, Fu);   // Fu earlier
        }
        unsigned Fe  = __shfl_up_sync(FULLMASK, Fi, 1);
        unsigned F31 = __shfl_sync(FULLMASK, Fi, 31);
        unsigned sin = (lane == 0) ? scar : ((Fe >> (scar << 3)) & 3u);
        scar = (F31 >> (scar << 3)) & 3u;

        unsigned spikes = (en.x >> (sin << 3)) & 0xffu;

        // ---- store (skip halo segments) ----
        if (seg >= HSEG) {
            if (INTERIOR) {
                float4 s0, s1;
                s0.x = (spikes &   1u) ? 1.0f : 0.0f;
                s0.y = (spikes &   2u) ? 1.0f : 0.0f;
                s0.z = (spikes &   4u) ? 1.0f : 0.0f;
                s0.w = (spikes &   8u) ? 1.0f : 0.0f;
                s1.x = (spikes &  16u) ? 1.0f : 0.0f;
                s1.y = (spikes &  32u) ? 1.0f : 0.0f;
                s1.z = (spikes &  64u) ? 1.0f : 0.0f;
                s1.w = (spikes & 128u) ? 1.0f : 0.0f;
                const int ox = seg * (WSEG / 4) + li;
                pO4[ox] = s0; pO4[ox + 1] = s1;
            } else {
                long long gg = base + (long long)seg * WSEG + lane * 8;
                #pragma unroll
                for (int t = 0; t < 8; t++) {
                    long long g = gg + t;
                    if (g >= 0 && g < N)
                        gOut[g] = ((spikes >> t) & 1u) ? 1.0f : 0.0f;
                }
            }
        }
    }
}

__global__ void __launch_bounds__(THREADS, 5)
neuron_kernel(const float* __restrict__ gI, const float* __restrict__ gU,
              const float* __restrict__ gTau, const float* __restrict__ gThr,
              float* __restrict__ gOut, int N, int nWT)
{
    __shared__ uint2 tbl[256];

    // ---- build 8-step refractory-DFA LUT (one entry per thread) ----
    {
        const unsigned e = threadIdx.x;   // THREADS == 256
        unsigned spAll = 0, mAll = 0;
        #pragma unroll
        for (int s0 = 0; s0 < 3; s0++) {
            int s = s0;
            unsigned sp = 0;
            #pragma unroll
            for (int k = 0; k < 8; k++) {
                bool fire = (s == 0) && ((e >> k) & 1u);
                if (fire) sp |= 1u << k;
                s = fire ? 2 : (s > 0 ? s - 1 : 0);
            }
            spAll |= sp << (8 * s0);
            mAll  |= (unsigned)s << (8 * s0);
        }
        tbl[e] = make_uint2(spAll, mAll);
    }
    __syncthreads();

    const int gwarp = (int)((blockIdx.x * blockDim.x + threadIdx.x) >> 5);
    if (gwarp >= nWT) return;                       // whole-warp uniform exit
    const int lane = threadIdx.x & 31;

    const float alpha = __fdiv_rn(1.0f, gTau[0]);
    const float rthr  = __fdiv_rn(1.0f, gThr[0]);
    const float a     = 1.0f - alpha;

    const long long base = (long long)gwarp * WTILE - WHALO;
    const bool interior = (base >= 1) && (base + WREGION <= (long long)N);

    if (interior)
        run_warp<true >(gI, gU, gOut, tbl, base, N, alpha, a, rthr, lane);
    else
        run_warp<false>(gI, gU, gOut, tbl, base, N, alpha, a, rthr, lane);
}

extern "C" void kernel_launch(void* const* d_in, const int* in_sizes, int n_in,
                              void* d_out, int out_size)
{
    const float* I   = (const float*)d_in[0];
    const float* u   = (const float*)d_in[1];
    const float* tau = (const float*)d_in[2];
    const float* thr = (const float*)d_in[3];
    float* out = (float*)d_out;
    const int N = in_sizes[0];

    const int nWT = (N + WTILE - 1) / WTILE;                // 5462 warp tiles
    const int blocks = (nWT * 32 + THREADS - 1) / THREADS;  // 683

    neuron_kernel<<<blocks, THREADS>>>(I, u, tau, thr, out, N, nWT);
}